// round 1
// baseline (speedup 1.0000x reference)
#include <cuda_runtime.h>

#define NATOMS_V 100
#define DIM    200
#define DIMP   208   // padded smem row stride (floats)
#define LHID   6
#define LOUT   3
#define LPRED  3
#define NADD   4
#define DPRED  204   // DIM + NADD
#define BMOL   256
#define NA     32
#define NTOT   8192

struct SmemLayout {
    float bufA[NA][DIMP];      // atom vectors (av)
    float bufB[NA][DIMP];      // hidden vectors (hv)
    float d2s[NA][NA];         // squared intra-molecule distances
    float Msm[NA][NA + 1];     // per-layer message matrix
    float gam[LHID][NA];       // gamma per layer per column-atom
    float pv[2][DPRED + 4];    // molecule vector ping-pong
    float red[8];
    int   at[NA];
};

// hv[i][c] = relu(bias[c] + sum_k src[i][k] * W[k*DIM + c])
// warp w -> rows 4w..4w+3 ; lane -> column pairs {2l+64u, 2l+64u+1}, u=0..3
__device__ __forceinline__ void block_gemm_relu(const float (*src)[DIMP],
                                                const float* __restrict__ W,
                                                const float* __restrict__ bias,
                                                float (*dst)[DIMP], int tid)
{
    const int w = tid >> 5, lane = tid & 31, i0 = w * 4;
    const bool has3 = (lane < 4);          // u=3 covers cols 192..199 only
    float2 acc[4][4];
    #pragma unroll
    for (int r = 0; r < 4; r++)
        #pragma unroll
        for (int u = 0; u < 4; u++) acc[r][u] = make_float2(0.f, 0.f);

    #pragma unroll 2
    for (int k = 0; k < DIM; k++) {
        const float a0 = src[i0 + 0][k];   // LDS broadcast across warp
        const float a1 = src[i0 + 1][k];
        const float a2 = src[i0 + 2][k];
        const float a3 = src[i0 + 3][k];
        const float* Wk = W + k * DIM;
        #pragma unroll
        for (int u = 0; u < 3; u++) {
            float2 wv = *(const float2*)(Wk + 2 * lane + 64 * u);  // coalesced LDG.64
            acc[0][u].x += a0 * wv.x; acc[0][u].y += a0 * wv.y;
            acc[1][u].x += a1 * wv.x; acc[1][u].y += a1 * wv.y;
            acc[2][u].x += a2 * wv.x; acc[2][u].y += a2 * wv.y;
            acc[3][u].x += a3 * wv.x; acc[3][u].y += a3 * wv.y;
        }
        if (has3) {
            float2 wv = *(const float2*)(Wk + 192 + 2 * lane);
            acc[0][3].x += a0 * wv.x; acc[0][3].y += a0 * wv.y;
            acc[1][3].x += a1 * wv.x; acc[1][3].y += a1 * wv.y;
            acc[2][3].x += a2 * wv.x; acc[2][3].y += a2 * wv.y;
            acc[3][3].x += a3 * wv.x; acc[3][3].y += a3 * wv.y;
        }
    }
    #pragma unroll
    for (int u = 0; u < 4; u++) {
        const int c = 2 * lane + 64 * u;
        if (c < DIM) {
            float2 bv = *(const float2*)(bias + c);
            #pragma unroll
            for (int r = 0; r < 4; r++) {
                float x = acc[r][u].x + bv.x;
                float y = acc[r][u].y + bv.y;
                *(float2*)&dst[i0 + r][c] = make_float2(fmaxf(x, 0.f), fmaxf(y, 0.f));
            }
        }
    }
}

// dst[i][c] = normalize_row( hv[i][c] + sum_j M[i][j]*hv[j][c] )
__device__ __forceinline__ void mix_normalize(const float (*hv)[DIMP],
                                              const float Msm[NA][NA + 1],
                                              float (*dst)[DIMP], int tid)
{
    const int w = tid >> 5, lane = tid & 31, i0 = w * 4;
    const bool has3 = (lane < 4);
    float2 acc[4][4];
    #pragma unroll
    for (int r = 0; r < 4; r++) {
        #pragma unroll
        for (int u = 0; u < 3; u++)
            acc[r][u] = *(const float2*)&hv[i0 + r][2 * lane + 64 * u];
        acc[r][3] = has3 ? *(const float2*)&hv[i0 + r][192 + 2 * lane]
                         : make_float2(0.f, 0.f);
    }
    #pragma unroll 4
    for (int j = 0; j < NA; j++) {
        const float m0 = Msm[i0 + 0][j];
        const float m1 = Msm[i0 + 1][j];
        const float m2 = Msm[i0 + 2][j];
        const float m3 = Msm[i0 + 3][j];
        #pragma unroll
        for (int u = 0; u < 3; u++) {
            float2 h = *(const float2*)&hv[j][2 * lane + 64 * u];
            acc[0][u].x += m0 * h.x; acc[0][u].y += m0 * h.y;
            acc[1][u].x += m1 * h.x; acc[1][u].y += m1 * h.y;
            acc[2][u].x += m2 * h.x; acc[2][u].y += m2 * h.y;
            acc[3][u].x += m3 * h.x; acc[3][u].y += m3 * h.y;
        }
        if (has3) {
            float2 h = *(const float2*)&hv[j][192 + 2 * lane];
            acc[0][3].x += m0 * h.x; acc[0][3].y += m0 * h.y;
            acc[1][3].x += m1 * h.x; acc[1][3].y += m1 * h.y;
            acc[2][3].x += m2 * h.x; acc[2][3].y += m2 * h.y;
            acc[3][3].x += m3 * h.x; acc[3][3].y += m3 * h.y;
        }
    }
    #pragma unroll
    for (int r = 0; r < 4; r++) {
        float ss = 0.f;
        #pragma unroll
        for (int u = 0; u < 4; u++)
            ss += acc[r][u].x * acc[r][u].x + acc[r][u].y * acc[r][u].y;
        #pragma unroll
        for (int o = 16; o > 0; o >>= 1)
            ss += __shfl_xor_sync(0xffffffffu, ss, o);
        const float scale = 1.f / fmaxf(sqrtf(ss), 1e-12f);
        #pragma unroll
        for (int u = 0; u < 3; u++) {
            const int c = 2 * lane + 64 * u;
            *(float2*)&dst[i0 + r][c] =
                make_float2(acc[r][u].x * scale, acc[r][u].y * scale);
        }
        if (has3)
            *(float2*)&dst[i0 + r][192 + 2 * lane] =
                make_float2(acc[r][3].x * scale, acc[r][3].y * scale);
    }
}

__global__ __launch_bounds__(256, 2)
void mgnn_kernel(const int*   __restrict__ atoms,
                 const float* __restrict__ dist,
                 const float* __restrict__ adducts,
                 const float* __restrict__ embed_atom,
                 const float* __restrict__ gamma_tab,
                 const float* __restrict__ W_atom_w,
                 const float* __restrict__ W_atom_b,
                 const float* __restrict__ W_out_w,
                 const float* __restrict__ W_out_b,
                 const float* __restrict__ W_pred_w,
                 const float* __restrict__ W_pred_b,
                 const float* __restrict__ W_prop_w,
                 const float* __restrict__ W_prop_b,
                 float* __restrict__ out)
{
    extern __shared__ char smem_raw[];
    SmemLayout& sm = *reinterpret_cast<SmemLayout*>(smem_raw);

    const int m = blockIdx.x;
    const int tid = threadIdx.x;
    const int base = m * NA;

    // ---- setup: atoms, embeddings, intra-molecule d^2 block, gammas ----
    if (tid < NA) sm.at[tid] = atoms[base + tid];
    __syncthreads();
    for (int idx = tid; idx < NA * DIM; idx += 256) {
        const int i = idx / DIM, k = idx - i * DIM;
        sm.bufA[i][k] = embed_atom[sm.at[i] * DIM + k];
    }
    for (int idx = tid; idx < NA * NA; idx += 256) {
        const int i = idx >> 5, j = idx & 31;
        const float d = dist[(base + i) * NTOT + base + j];
        sm.d2s[i][j] = d * d;
    }
    for (int idx = tid; idx < LHID * NA; idx += 256) {
        const int l = idx >> 5, j = idx & 31;
        sm.gam[l][j] = gamma_tab[l * NATOMS_V + sm.at[j]];
    }
    __syncthreads();

    // ---- hidden layers: GEMM+relu, message mix, L2 row-normalize ----
    for (int l = 0; l < LHID; l++) {
        block_gemm_relu(sm.bufA, W_atom_w + l * DIM * DIM,
                        W_atom_b + l * DIM, sm.bufB, tid);
        __syncthreads();
        for (int idx = tid; idx < NA * NA; idx += 256) {
            const int i = idx >> 5, j = idx & 31;
            sm.Msm[i][j] = __expf(-sm.gam[l][j] * sm.d2s[i][j]);
        }
        __syncthreads();
        mix_normalize(sm.bufB, sm.Msm, sm.bufA, tid);
        __syncthreads();
    }

    // ---- output layers (relu MLP), ping-pong bufA <-> bufB ----
    block_gemm_relu(sm.bufA, W_out_w + 0 * DIM * DIM, W_out_b + 0 * DIM, sm.bufB, tid);
    __syncthreads();
    block_gemm_relu(sm.bufB, W_out_w + 1 * DIM * DIM, W_out_b + 1 * DIM, sm.bufA, tid);
    __syncthreads();
    block_gemm_relu(sm.bufA, W_out_w + 2 * DIM * DIM, W_out_b + 2 * DIM, sm.bufB, tid);
    __syncthreads();

    // ---- per-molecule sum + adducts ----
    if (tid < DIM) {
        float s = 0.f;
        #pragma unroll 8
        for (int i = 0; i < NA; i++) s += sm.bufB[i][tid];
        sm.pv[0][tid] = s;
    } else if (tid < DPRED) {
        sm.pv[0][tid] = adducts[m * NADD + (tid - DIM)];
    }
    __syncthreads();

    // ---- prediction MLP (1 x 204 @ 204 x 204), 3 layers ----
    int cur = 0;
    for (int l = 0; l < LPRED; l++) {
        if (tid < DPRED) {
            const float* Wp = W_pred_w + l * DPRED * DPRED;
            float acc = W_pred_b[l * DPRED + tid];
            #pragma unroll 4
            for (int k = 0; k < DPRED; k++)
                acc += sm.pv[cur][k] * Wp[k * DPRED + tid];
            sm.pv[cur ^ 1][tid] = fmaxf(acc, 0.f);
        }
        __syncthreads();
        cur ^= 1;
    }

    // ---- final scalar ----
    float part = (tid < DPRED) ? sm.pv[cur][tid] * W_prop_w[tid] : 0.f;
    #pragma unroll
    for (int o = 16; o > 0; o >>= 1)
        part += __shfl_xor_sync(0xffffffffu, part, o);
    if ((tid & 31) == 0) sm.red[tid >> 5] = part;
    __syncthreads();
    if (tid == 0) {
        float s = 0.f;
        #pragma unroll
        for (int w2 = 0; w2 < 8; w2++) s += sm.red[w2];
        out[m] = s + W_prop_b[0];
    }
}

extern "C" void kernel_launch(void* const* d_in, const int* in_sizes, int n_in,
                              void* d_out, int out_size)
{
    const int*   atoms      = (const int*)  d_in[0];
    const float* dist       = (const float*)d_in[1];
    const float* adducts    = (const float*)d_in[2];
    const float* embed_atom = (const float*)d_in[3];
    const float* gamma_tab  = (const float*)d_in[4];
    const float* W_atom_w   = (const float*)d_in[5];
    const float* W_atom_b   = (const float*)d_in[6];
    const float* W_out_w    = (const float*)d_in[7];
    const float* W_out_b    = (const float*)d_in[8];
    const float* W_pred_w   = (const float*)d_in[9];
    const float* W_pred_b   = (const float*)d_in[10];
    const float* W_prop_w   = (const float*)d_in[11];
    const float* W_prop_b   = (const float*)d_in[12];
    float* out = (float*)d_out;

    const int smem_bytes = (int)sizeof(SmemLayout);
    cudaFuncSetAttribute(mgnn_kernel,
                         cudaFuncAttributeMaxDynamicSharedMemorySize, smem_bytes);
    mgnn_kernel<<<BMOL, 256, smem_bytes>>>(
        atoms, dist, adducts, embed_atom, gamma_tab,
        W_atom_w, W_atom_b, W_out_w, W_out_b,
        W_pred_w, W_pred_b, W_prop_w, W_prop_b, out);
}